// round 3
// baseline (speedup 1.0000x reference)
#include <cuda_runtime.h>
#include <math.h>
#include <stdint.h>

// Problem constants
#define T_TOK 8192      // B*S tokens
#define DIM   768       // d_model
#define FDIM  3072      // ffn dim
#define NEXP  8
#define NPAIR (T_TOK*2) // token-expert pairs (top-2)
#define NOUT  (T_TOK*DIM)

// ---------------- scratch (static device globals; no allocation) ------------
__device__ float g_H[(size_t)NPAIR * FDIM];   // 201 MB hidden activations
__device__ float g_Y[(size_t)NPAIR * DIM];    // 50 MB  per-pair outputs
__device__ int   g_eid[NPAIR];
__device__ float g_gate[NPAIR];
__device__ int   g_rows[NPAIR];               // token id at compact position
__device__ int   g_ppos[NPAIR];               // pair -> compact position
__device__ int   g_counts[NEXP];
__device__ int   g_offs[NEXP];
__device__ int   g_cursor[NEXP];
__device__ float g_sumprob[NEXP];
__device__ float g_zsum;

__device__ __forceinline__ float gelu_exact(float v) {
    return 0.5f * v * (1.0f + erff(v * 0.70710678118654752f));
}

// ---------------- init: zero small accumulators -----------------------------
__global__ void init_kernel() {
    int i = threadIdx.x;
    if (i < NEXP) { g_counts[i] = 0; g_cursor[i] = 0; g_sumprob[i] = 0.0f; }
    if (i == 0)   { g_zsum = 0.0f; }
}

// ---------------- router: logits, softmax, top-2, loss partials --------------
__global__ void router_kernel(const float* __restrict__ x,
                              const float* __restrict__ Wr) {
    __shared__ float wr_s[DIM * NEXP];       // 24 KB
    __shared__ float s_prob[NEXP];
    __shared__ float s_z;

    for (int i = threadIdx.x; i < DIM * NEXP; i += blockDim.x)
        wr_s[i] = Wr[i];
    if (threadIdx.x < NEXP) s_prob[threadIdx.x] = 0.0f;
    if (threadIdx.x == 0)   s_z = 0.0f;
    __syncthreads();

    const int warp = threadIdx.x >> 5;
    const int lane = threadIdx.x & 31;
    const int WPB  = blockDim.x >> 5;

    for (int t = blockIdx.x * WPB + warp; t < T_TOK; t += gridDim.x * WPB) {
        float acc[NEXP];
        #pragma unroll
        for (int e = 0; e < NEXP; e++) acc[e] = 0.0f;

        const float4* xr = (const float4*)(x + (size_t)t * DIM);
        #pragma unroll
        for (int i = 0; i < DIM / 128; i++) {
            float4 v = xr[i * 32 + lane];
            int d0 = i * 128 + lane * 4;
            const float* vp = &v.x;
            #pragma unroll
            for (int j = 0; j < 4; j++) {
                float xv = vp[j];
                const float* w = &wr_s[(d0 + j) * NEXP];
                #pragma unroll
                for (int e = 0; e < NEXP; e++) acc[e] += xv * w[e];
            }
        }
        #pragma unroll
        for (int e = 0; e < NEXP; e++) {
            #pragma unroll
            for (int o = 16; o > 0; o >>= 1)
                acc[e] += __shfl_xor_sync(0xffffffffu, acc[e], o);
        }
        if (lane == 0) {
            float m = acc[0];
            #pragma unroll
            for (int e = 1; e < NEXP; e++) m = fmaxf(m, acc[e]);
            float denom = 0.0f;
            float p[NEXP];
            #pragma unroll
            for (int e = 0; e < NEXP; e++) { p[e] = expf(acc[e] - m); denom += p[e]; }
            float inv = 1.0f / denom;
            #pragma unroll
            for (int e = 0; e < NEXP; e++) p[e] *= inv;
            float lse = m + logf(denom);
            atomicAdd(&s_z, lse * lse);
            #pragma unroll
            for (int e = 0; e < NEXP; e++) atomicAdd(&s_prob[e], p[e]);

            // top-2 (first-index wins on ties, like lax.top_k)
            int e0 = 0;
            #pragma unroll
            for (int e = 1; e < NEXP; e++) if (p[e] > p[e0]) e0 = e;
            int e1 = (e0 == 0) ? 1 : 0;
            #pragma unroll
            for (int e = 0; e < NEXP; e++)
                if (e != e0 && p[e] > p[e1]) e1 = e;
            float s = p[e0] + p[e1] + 1e-8f;
            g_eid[2 * t]      = e0;
            g_eid[2 * t + 1]  = e1;
            g_gate[2 * t]     = p[e0] / s;
            g_gate[2 * t + 1] = p[e1] / s;
            atomicAdd(&g_counts[e0], 1);
            atomicAdd(&g_counts[e1], 1);
        }
    }
    __syncthreads();
    if (threadIdx.x < NEXP) atomicAdd(&g_sumprob[threadIdx.x], s_prob[threadIdx.x]);
    if (threadIdx.x == 0)   atomicAdd(&g_zsum, s_z);
}

// ---------------- tiny exclusive scan over 8 expert counts -------------------
__global__ void scan_kernel() {
    if (threadIdx.x == 0 && blockIdx.x == 0) {
        int o = 0;
        for (int e = 0; e < NEXP; e++) {
            g_offs[e] = o; g_cursor[e] = o; o += g_counts[e];
        }
    }
}

// ---------------- scatter pairs into compact per-expert buckets -------------
__global__ void scatter_kernel() {
    int i = blockIdx.x * blockDim.x + threadIdx.x;
    if (i < NPAIR) {
        int e   = g_eid[i];
        int pos = atomicAdd(&g_cursor[e], 1);
        g_rows[pos] = i >> 1;   // token id
        g_ppos[i]   = pos;
    }
}

// ---------------- FFN1: H = gelu(X_gathered @ W1[e] + b1[e]) ----------------
// 128x128 tile, BK=8, 256 threads, 8x8 register microtile.
__global__ void __launch_bounds__(256, 2)
ffn1_kernel(const float* __restrict__ x, const float* __restrict__ W1,
            const float* __restrict__ b1) {
    const int e   = blockIdx.z;
    const int cnt = g_counts[e];
    const int m0  = blockIdx.y * 128;
    if (m0 >= cnt) return;
    const int n0  = blockIdx.x * 128;
    const int seg = g_offs[e];

    __shared__ float As[8][128];
    __shared__ float Bs[8][128];

    const int tid = threadIdx.x;
    const int tx  = tid & 15;        // 0..15  -> N microtile
    const int ty  = tid >> 4;        // 0..15  -> M microtile

    // A loader: row = tid/2, quarter kq = tid&1 (float4 at k0 + kq*4)
    const int ra = tid >> 1;
    const int kq = tid & 1;
    int lm = m0 + ra;
    int tok = g_rows[seg + min(lm, cnt - 1)];
    const float* arow = x + (size_t)tok * DIM;

    // B loader: k = tid/32, n = (tid&31)*4
    const int bk = tid >> 5;
    const int bn = (tid & 31) * 4;
    const float* bbase = W1 + (size_t)e * DIM * FDIM + n0;

    float acc[8][8];
    #pragma unroll
    for (int i = 0; i < 8; i++)
        #pragma unroll
        for (int j = 0; j < 8; j++) acc[i][j] = 0.0f;

    for (int k0 = 0; k0 < DIM; k0 += 8) {
        float4 av = *(const float4*)(arow + k0 + kq * 4);
        float4 bv = *(const float4*)(bbase + (size_t)(k0 + bk) * FDIM + bn);
        As[kq * 4 + 0][ra] = av.x;
        As[kq * 4 + 1][ra] = av.y;
        As[kq * 4 + 2][ra] = av.z;
        As[kq * 4 + 3][ra] = av.w;
        *(float4*)&Bs[bk][bn] = bv;
        __syncthreads();
        #pragma unroll
        for (int k = 0; k < 8; k++) {
            float a[8], b[8];
            *(float4*)&a[0] = *(const float4*)&As[k][ty * 8];
            *(float4*)&a[4] = *(const float4*)&As[k][ty * 8 + 4];
            *(float4*)&b[0] = *(const float4*)&Bs[k][tx * 8];
            *(float4*)&b[4] = *(const float4*)&Bs[k][tx * 8 + 4];
            #pragma unroll
            for (int i = 0; i < 8; i++)
                #pragma unroll
                for (int j = 0; j < 8; j++) acc[i][j] += a[i] * b[j];
        }
        __syncthreads();
    }

    const float* b1p = b1 + (size_t)e * FDIM + n0 + tx * 8;
    float bias[8];
    #pragma unroll
    for (int j = 0; j < 8; j++) bias[j] = b1p[j];

    #pragma unroll
    for (int i = 0; i < 8; i++) {
        int lm2 = m0 + ty * 8 + i;
        if (lm2 >= cnt) continue;
        float* hr = g_H + (size_t)(seg + lm2) * FDIM + n0 + tx * 8;
        float v[8];
        #pragma unroll
        for (int j = 0; j < 8; j++) v[j] = gelu_exact(acc[i][j] + bias[j]);
        *(float4*)&hr[0] = *(float4*)&v[0];
        *(float4*)&hr[4] = *(float4*)&v[4];
    }
}

// ---------------- FFN2: Y = H @ W2[e] + b2[e] --------------------------------
__global__ void __launch_bounds__(256, 2)
ffn2_kernel(const float* __restrict__ W2, const float* __restrict__ b2) {
    const int e   = blockIdx.z;
    const int cnt = g_counts[e];
    const int m0  = blockIdx.y * 128;
    if (m0 >= cnt) return;
    const int n0  = blockIdx.x * 128;
    const int seg = g_offs[e];

    __shared__ float As[8][128];
    __shared__ float Bs[8][128];

    const int tid = threadIdx.x;
    const int tx  = tid & 15;
    const int ty  = tid >> 4;

    const int ra = tid >> 1;
    const int kq = tid & 1;
    int lm = m0 + ra;
    const float* arow = g_H + (size_t)(seg + min(lm, cnt - 1)) * FDIM;

    const int bk = tid >> 5;
    const int bn = (tid & 31) * 4;
    const float* bbase = W2 + (size_t)e * FDIM * DIM + n0;

    float acc[8][8];
    #pragma unroll
    for (int i = 0; i < 8; i++)
        #pragma unroll
        for (int j = 0; j < 8; j++) acc[i][j] = 0.0f;

    for (int k0 = 0; k0 < FDIM; k0 += 8) {
        float4 av = *(const float4*)(arow + k0 + kq * 4);
        float4 bv = *(const float4*)(bbase + (size_t)(k0 + bk) * DIM + bn);
        As[kq * 4 + 0][ra] = av.x;
        As[kq * 4 + 1][ra] = av.y;
        As[kq * 4 + 2][ra] = av.z;
        As[kq * 4 + 3][ra] = av.w;
        *(float4*)&Bs[bk][bn] = bv;
        __syncthreads();
        #pragma unroll
        for (int k = 0; k < 8; k++) {
            float a[8], b[8];
            *(float4*)&a[0] = *(const float4*)&As[k][ty * 8];
            *(float4*)&a[4] = *(const float4*)&As[k][ty * 8 + 4];
            *(float4*)&b[0] = *(const float4*)&Bs[k][tx * 8];
            *(float4*)&b[4] = *(const float4*)&Bs[k][tx * 8 + 4];
            #pragma unroll
            for (int i = 0; i < 8; i++)
                #pragma unroll
                for (int j = 0; j < 8; j++) acc[i][j] += a[i] * b[j];
        }
        __syncthreads();
    }

    const float* b2p = b2 + (size_t)e * DIM + n0 + tx * 8;
    float bias[8];
    #pragma unroll
    for (int j = 0; j < 8; j++) bias[j] = b2p[j];

    #pragma unroll
    for (int i = 0; i < 8; i++) {
        int lm2 = m0 + ty * 8 + i;
        if (lm2 >= cnt) continue;
        float* yr = g_Y + (size_t)(seg + lm2) * DIM + n0 + tx * 8;
        float v[8];
        #pragma unroll
        for (int j = 0; j < 8; j++) v[j] = acc[i][j] + bias[j];
        *(float4*)&yr[0] = *(float4*)&v[0];
        *(float4*)&yr[4] = *(float4*)&v[4];
    }
}

// ---------------- combine: out[t] = g0*Y[pos0] + g1*Y[pos1] -----------------
__global__ void combine_kernel(float* __restrict__ out) {
    const int NV = NOUT / 4;   // float4 elements
    int idx = blockIdx.x * blockDim.x + threadIdx.x;
    if (idx >= NV) return;
    int t = idx / (DIM / 4);
    int q = idx % (DIM / 4);
    int p0 = g_ppos[2 * t], p1 = g_ppos[2 * t + 1];
    float g0 = g_gate[2 * t], g1 = g_gate[2 * t + 1];
    float4 y0 = ((const float4*)(g_Y + (size_t)p0 * DIM))[q];
    float4 y1 = ((const float4*)(g_Y + (size_t)p1 * DIM))[q];
    float4 o;
    o.x = g0 * y0.x + g1 * y1.x;
    o.y = g0 * y0.y + g1 * y1.y;
    o.z = g0 * y0.z + g1 * y1.z;
    o.w = g0 * y0.w + g1 * y1.w;
    ((float4*)out)[idx] = o;
}

// ---------------- finalize: aux losses ---------------------------------------
__global__ void finalize_kernel(float* __restrict__ out, int out_size) {
    if (threadIdx.x != 0 || blockIdx.x != 0) return;
    float u[NEXP];
    float mean = 0.0f;
    #pragma unroll
    for (int e = 0; e < NEXP; e++) { u[e] = g_sumprob[e] / (float)T_TOK; mean += u[e]; }
    mean /= (float)NEXP;
    float var = 0.0f;
    #pragma unroll
    for (int e = 0; e < NEXP; e++) { float d = u[e] - mean; var += d * d; }
    var /= (float)NEXP;
    float lb = var / (mean * mean + 1e-8f) * (float)NEXP * 0.01f;
    float z  = (g_zsum / (float)T_TOK) * 0.001f;
    if (out_size >= NOUT + 1) out[NOUT] = lb;
    if (out_size >= NOUT + 2) out[NOUT + 1] = z;
}

// ---------------- launch ------------------------------------------------------
extern "C" void kernel_launch(void* const* d_in, const int* in_sizes, int n_in,
                              void* d_out, int out_size) {
    const float* x  = (const float*)d_in[0];
    const float* Wr = (const float*)d_in[1];
    const float* W1 = (const float*)d_in[2];
    const float* b1 = (const float*)d_in[3];
    const float* W2 = (const float*)d_in[4];
    const float* b2 = (const float*)d_in[5];
    float* out = (float*)d_out;
    (void)in_sizes; (void)n_in;

    init_kernel<<<1, 32>>>();
    router_kernel<<<128, 256>>>(x, Wr);
    scan_kernel<<<1, 32>>>();
    scatter_kernel<<<(NPAIR + 255) / 256, 256>>>();

    dim3 g1(FDIM / 128, T_TOK / 128, NEXP);   // (24, 64, 8)
    ffn1_kernel<<<g1, 256>>>(x, W1, b1);
    dim3 g2(DIM / 128, T_TOK / 128, NEXP);    // (6, 64, 8)
    ffn2_kernel<<<g2, 256>>>(W2, b2);

    combine_kernel<<<(NOUT / 4 + 255) / 256, 256>>>(out);
    finalize_kernel<<<1, 32>>>(out, out_size);
}

// round 5
// speedup vs baseline: 1.0001x; 1.0001x over previous
#include <cuda_runtime.h>
#include <math.h>
#include <stdint.h>

// Problem constants
#define T_TOK 8192      // B*S tokens
#define DIM   768       // d_model
#define FDIM  3072      // ffn dim
#define NEXP  8
#define NPAIR (T_TOK*2) // token-expert pairs (top-2)
#define NOUT  (T_TOK*DIM)

// ---------------- scratch (static device globals; no allocation) ------------
__device__ float g_H[(size_t)NPAIR * FDIM];   // 201 MB hidden activations
__device__ float g_Y[(size_t)NPAIR * DIM];    // 50 MB  per-pair outputs
__device__ int   g_eid[NPAIR];
__device__ float g_gate[NPAIR];
__device__ int   g_rows[NPAIR];               // token id at compact position
__device__ int   g_ppos[NPAIR];               // pair -> compact position
__device__ int   g_counts[NEXP];
__device__ int   g_offs[NEXP];
__device__ int   g_cursor[NEXP];
__device__ float g_sumprob[NEXP];
__device__ float g_zsum;

__device__ __forceinline__ float gelu_exact(float v) {
    return 0.5f * v * (1.0f + erff(v * 0.70710678118654752f));
}

// ---------------- init: zero small accumulators -----------------------------
__global__ void init_kernel() {
    int i = threadIdx.x;
    if (i < NEXP) { g_counts[i] = 0; g_cursor[i] = 0; g_sumprob[i] = 0.0f; }
    if (i == 0)   { g_zsum = 0.0f; }
}

// ---------------- router: logits, softmax, top-2, loss partials --------------
__global__ void router_kernel(const float* __restrict__ x,
                              const float* __restrict__ Wr) {
    __shared__ float wr_s[DIM * NEXP];       // 24 KB
    __shared__ float s_prob[NEXP];
    __shared__ float s_z;

    for (int i = threadIdx.x; i < DIM * NEXP; i += blockDim.x)
        wr_s[i] = Wr[i];
    if (threadIdx.x < NEXP) s_prob[threadIdx.x] = 0.0f;
    if (threadIdx.x == 0)   s_z = 0.0f;
    __syncthreads();

    const int warp = threadIdx.x >> 5;
    const int lane = threadIdx.x & 31;
    const int WPB  = blockDim.x >> 5;

    for (int t = blockIdx.x * WPB + warp; t < T_TOK; t += gridDim.x * WPB) {
        float acc[NEXP];
        #pragma unroll
        for (int e = 0; e < NEXP; e++) acc[e] = 0.0f;

        const float4* xr = (const float4*)(x + (size_t)t * DIM);
        #pragma unroll
        for (int i = 0; i < DIM / 128; i++) {
            float4 v = xr[i * 32 + lane];
            int d0 = i * 128 + lane * 4;
            const float* vp = &v.x;
            #pragma unroll
            for (int j = 0; j < 4; j++) {
                float xv = vp[j];
                const float* w = &wr_s[(d0 + j) * NEXP];
                #pragma unroll
                for (int e = 0; e < NEXP; e++) acc[e] += xv * w[e];
            }
        }
        #pragma unroll
        for (int e = 0; e < NEXP; e++) {
            #pragma unroll
            for (int o = 16; o > 0; o >>= 1)
                acc[e] += __shfl_xor_sync(0xffffffffu, acc[e], o);
        }
        if (lane == 0) {
            float m = acc[0];
            #pragma unroll
            for (int e = 1; e < NEXP; e++) m = fmaxf(m, acc[e]);
            float denom = 0.0f;
            float p[NEXP];
            #pragma unroll
            for (int e = 0; e < NEXP; e++) { p[e] = expf(acc[e] - m); denom += p[e]; }
            float inv = 1.0f / denom;
            #pragma unroll
            for (int e = 0; e < NEXP; e++) p[e] *= inv;
            float lse = m + logf(denom);
            atomicAdd(&s_z, lse * lse);
            #pragma unroll
            for (int e = 0; e < NEXP; e++) atomicAdd(&s_prob[e], p[e]);

            // top-2 (first-index wins on ties, like lax.top_k)
            int e0 = 0;
            #pragma unroll
            for (int e = 1; e < NEXP; e++) if (p[e] > p[e0]) e0 = e;
            int e1 = (e0 == 0) ? 1 : 0;
            #pragma unroll
            for (int e = 0; e < NEXP; e++)
                if (e != e0 && p[e] > p[e1]) e1 = e;
            float s = p[e0] + p[e1] + 1e-8f;
            g_eid[2 * t]      = e0;
            g_eid[2 * t + 1]  = e1;
            g_gate[2 * t]     = p[e0] / s;
            g_gate[2 * t + 1] = p[e1] / s;
            atomicAdd(&g_counts[e0], 1);
            atomicAdd(&g_counts[e1], 1);
        }
    }
    __syncthreads();
    if (threadIdx.x < NEXP) atomicAdd(&g_sumprob[threadIdx.x], s_prob[threadIdx.x]);
    if (threadIdx.x == 0)   atomicAdd(&g_zsum, s_z);
}

// ---------------- tiny exclusive scan over 8 expert counts -------------------
__global__ void scan_kernel() {
    if (threadIdx.x == 0 && blockIdx.x == 0) {
        int o = 0;
        for (int e = 0; e < NEXP; e++) {
            g_offs[e] = o; g_cursor[e] = o; o += g_counts[e];
        }
    }
}

// ---------------- scatter pairs into compact per-expert buckets -------------
__global__ void scatter_kernel() {
    int i = blockIdx.x * blockDim.x + threadIdx.x;
    if (i < NPAIR) {
        int e   = g_eid[i];
        int pos = atomicAdd(&g_cursor[e], 1);
        g_rows[pos] = i >> 1;   // token id
        g_ppos[i]   = pos;
    }
}

// ---------------- FFN1: H = gelu(X_gathered @ W1[e] + b1[e]) ----------------
// 128x128 tile, BK=8, 256 threads, 8x8 register microtile.
__global__ void __launch_bounds__(256, 2)
ffn1_kernel(const float* __restrict__ x, const float* __restrict__ W1,
            const float* __restrict__ b1) {
    const int e   = blockIdx.z;
    const int cnt = g_counts[e];
    const int m0  = blockIdx.y * 128;
    if (m0 >= cnt) return;
    const int n0  = blockIdx.x * 128;
    const int seg = g_offs[e];

    __shared__ float As[8][128];
    __shared__ float Bs[8][128];

    const int tid = threadIdx.x;
    const int tx  = tid & 15;        // 0..15  -> N microtile
    const int ty  = tid >> 4;        // 0..15  -> M microtile

    // A loader: row = tid/2, quarter kq = tid&1 (float4 at k0 + kq*4)
    const int ra = tid >> 1;
    const int kq = tid & 1;
    int lm = m0 + ra;
    int tok = g_rows[seg + min(lm, cnt - 1)];
    const float* arow = x + (size_t)tok * DIM;

    // B loader: k = tid/32, n = (tid&31)*4
    const int bk = tid >> 5;
    const int bn = (tid & 31) * 4;
    const float* bbase = W1 + (size_t)e * DIM * FDIM + n0;

    float acc[8][8];
    #pragma unroll
    for (int i = 0; i < 8; i++)
        #pragma unroll
        for (int j = 0; j < 8; j++) acc[i][j] = 0.0f;

    for (int k0 = 0; k0 < DIM; k0 += 8) {
        float4 av = *(const float4*)(arow + k0 + kq * 4);
        float4 bv = *(const float4*)(bbase + (size_t)(k0 + bk) * FDIM + bn);
        As[kq * 4 + 0][ra] = av.x;
        As[kq * 4 + 1][ra] = av.y;
        As[kq * 4 + 2][ra] = av.z;
        As[kq * 4 + 3][ra] = av.w;
        *(float4*)&Bs[bk][bn] = bv;
        __syncthreads();
        #pragma unroll
        for (int k = 0; k < 8; k++) {
            float a[8], b[8];
            *(float4*)&a[0] = *(const float4*)&As[k][ty * 8];
            *(float4*)&a[4] = *(const float4*)&As[k][ty * 8 + 4];
            *(float4*)&b[0] = *(const float4*)&Bs[k][tx * 8];
            *(float4*)&b[4] = *(const float4*)&Bs[k][tx * 8 + 4];
            #pragma unroll
            for (int i = 0; i < 8; i++)
                #pragma unroll
                for (int j = 0; j < 8; j++) acc[i][j] += a[i] * b[j];
        }
        __syncthreads();
    }

    const float* b1p = b1 + (size_t)e * FDIM + n0 + tx * 8;
    float bias[8];
    #pragma unroll
    for (int j = 0; j < 8; j++) bias[j] = b1p[j];

    #pragma unroll
    for (int i = 0; i < 8; i++) {
        int lm2 = m0 + ty * 8 + i;
        if (lm2 >= cnt) continue;
        float* hr = g_H + (size_t)(seg + lm2) * FDIM + n0 + tx * 8;
        float v[8];
        #pragma unroll
        for (int j = 0; j < 8; j++) v[j] = gelu_exact(acc[i][j] + bias[j]);
        *(float4*)&hr[0] = *(float4*)&v[0];
        *(float4*)&hr[4] = *(float4*)&v[4];
    }
}

// ---------------- FFN2: Y = H @ W2[e] + b2[e] --------------------------------
__global__ void __launch_bounds__(256, 2)
ffn2_kernel(const float* __restrict__ W2, const float* __restrict__ b2) {
    const int e   = blockIdx.z;
    const int cnt = g_counts[e];
    const int m0  = blockIdx.y * 128;
    if (m0 >= cnt) return;
    const int n0  = blockIdx.x * 128;
    const int seg = g_offs[e];

    __shared__ float As[8][128];
    __shared__ float Bs[8][128];

    const int tid = threadIdx.x;
    const int tx  = tid & 15;
    const int ty  = tid >> 4;

    const int ra = tid >> 1;
    const int kq = tid & 1;
    int lm = m0 + ra;
    const float* arow = g_H + (size_t)(seg + min(lm, cnt - 1)) * FDIM;

    const int bk = tid >> 5;
    const int bn = (tid & 31) * 4;
    const float* bbase = W2 + (size_t)e * FDIM * DIM + n0;

    float acc[8][8];
    #pragma unroll
    for (int i = 0; i < 8; i++)
        #pragma unroll
        for (int j = 0; j < 8; j++) acc[i][j] = 0.0f;

    for (int k0 = 0; k0 < FDIM; k0 += 8) {
        float4 av = *(const float4*)(arow + k0 + kq * 4);
        float4 bv = *(const float4*)(bbase + (size_t)(k0 + bk) * DIM + bn);
        As[kq * 4 + 0][ra] = av.x;
        As[kq * 4 + 1][ra] = av.y;
        As[kq * 4 + 2][ra] = av.z;
        As[kq * 4 + 3][ra] = av.w;
        *(float4*)&Bs[bk][bn] = bv;
        __syncthreads();
        #pragma unroll
        for (int k = 0; k < 8; k++) {
            float a[8], b[8];
            *(float4*)&a[0] = *(const float4*)&As[k][ty * 8];
            *(float4*)&a[4] = *(const float4*)&As[k][ty * 8 + 4];
            *(float4*)&b[0] = *(const float4*)&Bs[k][tx * 8];
            *(float4*)&b[4] = *(const float4*)&Bs[k][tx * 8 + 4];
            #pragma unroll
            for (int i = 0; i < 8; i++)
                #pragma unroll
                for (int j = 0; j < 8; j++) acc[i][j] += a[i] * b[j];
        }
        __syncthreads();
    }

    const float* b2p = b2 + (size_t)e * DIM + n0 + tx * 8;
    float bias[8];
    #pragma unroll
    for (int j = 0; j < 8; j++) bias[j] = b2p[j];

    #pragma unroll
    for (int i = 0; i < 8; i++) {
        int lm2 = m0 + ty * 8 + i;
        if (lm2 >= cnt) continue;
        float* yr = g_Y + (size_t)(seg + lm2) * DIM + n0 + tx * 8;
        float v[8];
        #pragma unroll
        for (int j = 0; j < 8; j++) v[j] = acc[i][j] + bias[j];
        *(float4*)&yr[0] = *(float4*)&v[0];
        *(float4*)&yr[4] = *(float4*)&v[4];
    }
}

// ---------------- combine: out[t] = g0*Y[pos0] + g1*Y[pos1] -----------------
__global__ void combine_kernel(float* __restrict__ out) {
    const int NV = NOUT / 4;   // float4 elements
    int idx = blockIdx.x * blockDim.x + threadIdx.x;
    if (idx >= NV) return;
    int t = idx / (DIM / 4);
    int q = idx % (DIM / 4);
    int p0 = g_ppos[2 * t], p1 = g_ppos[2 * t + 1];
    float g0 = g_gate[2 * t], g1 = g_gate[2 * t + 1];
    float4 y0 = ((const float4*)(g_Y + (size_t)p0 * DIM))[q];
    float4 y1 = ((const float4*)(g_Y + (size_t)p1 * DIM))[q];
    float4 o;
    o.x = g0 * y0.x + g1 * y1.x;
    o.y = g0 * y0.y + g1 * y1.y;
    o.z = g0 * y0.z + g1 * y1.z;
    o.w = g0 * y0.w + g1 * y1.w;
    ((float4*)out)[idx] = o;
}

// ---------------- finalize: aux losses ---------------------------------------
__global__ void finalize_kernel(float* __restrict__ out, int out_size) {
    if (threadIdx.x != 0 || blockIdx.x != 0) return;
    float u[NEXP];
    float mean = 0.0f;
    #pragma unroll
    for (int e = 0; e < NEXP; e++) { u[e] = g_sumprob[e] / (float)T_TOK; mean += u[e]; }
    mean /= (float)NEXP;
    float var = 0.0f;
    #pragma unroll
    for (int e = 0; e < NEXP; e++) { float d = u[e] - mean; var += d * d; }
    var /= (float)NEXP;
    float lb = var / (mean * mean + 1e-8f) * (float)NEXP * 0.01f;
    float z  = (g_zsum / (float)T_TOK) * 0.001f;
    if (out_size >= NOUT + 1) out[NOUT] = lb;
    if (out_size >= NOUT + 2) out[NOUT + 1] = z;
}

// ---------------- launch ------------------------------------------------------
extern "C" void kernel_launch(void* const* d_in, const int* in_sizes, int n_in,
                              void* d_out, int out_size) {
    const float* x  = (const float*)d_in[0];
    const float* Wr = (const float*)d_in[1];
    const float* W1 = (const float*)d_in[2];
    const float* b1 = (const float*)d_in[3];
    const float* W2 = (const float*)d_in[4];
    const float* b2 = (const float*)d_in[5];
    float* out = (float*)d_out;
    (void)in_sizes; (void)n_in;

    init_kernel<<<1, 32>>>();
    router_kernel<<<128, 256>>>(x, Wr);
    scan_kernel<<<1, 32>>>();
    scatter_kernel<<<(NPAIR + 255) / 256, 256>>>();

    dim3 g1(FDIM / 128, T_TOK / 128, NEXP);   // (24, 64, 8)
    ffn1_kernel<<<g1, 256>>>(x, W1, b1);
    dim3 g2(DIM / 128, T_TOK / 128, NEXP);    // (6, 64, 8)
    ffn2_kernel<<<g2, 256>>>(W2, b2);

    combine_kernel<<<(NOUT / 4 + 255) / 256, 256>>>(out);
    finalize_kernel<<<1, 32>>>(out, out_size);
}

// round 11
// speedup vs baseline: 2.1300x; 2.1297x over previous
#include <cuda_runtime.h>
#include <cuda_bf16.h>
#include <math.h>
#include <stdint.h>

#define T_TOK 8192
#define DIM   768
#define FDIM  3072
#define NEXP  8
#define NPAIR (T_TOK*2)
#define NOUT  (T_TOK*DIM)

// GEMM tile config
#define BK    32
#define LDA   40      // bf16 elems per A smem row (32 + 8 pad)
#define LDB   136     // bf16 elems per B smem row (128 + 8 pad)
#define A_LO_OFF 10240          // 128*40*2
#define B_HI_OFF 20480
#define B_LO_OFF 29184          // 20480 + 32*136*2
#define STAGE_B  37888          // 20480 + 2*8704
#define SMEM_BYTES (2*STAGE_B)  // 75776

// ---------------- scratch (static device globals; no allocation) ------------
__device__ __nv_bfloat16 g_Xhi[(size_t)T_TOK * DIM];
__device__ __nv_bfloat16 g_Xlo[(size_t)T_TOK * DIM];
__device__ __nv_bfloat16 g_W1hi[(size_t)NEXP * DIM * FDIM];
__device__ __nv_bfloat16 g_W1lo[(size_t)NEXP * DIM * FDIM];
__device__ __nv_bfloat16 g_W2hi[(size_t)NEXP * FDIM * DIM];
__device__ __nv_bfloat16 g_W2lo[(size_t)NEXP * FDIM * DIM];
__device__ __nv_bfloat16 g_Hhi[(size_t)NPAIR * FDIM];
__device__ __nv_bfloat16 g_Hlo[(size_t)NPAIR * FDIM];
__device__ float g_Y[(size_t)NPAIR * DIM];

__device__ int   g_eid[NPAIR];
__device__ float g_gate[NPAIR];
__device__ int   g_rows[NPAIR];
__device__ int   g_ppos[NPAIR];
__device__ int   g_counts[NEXP];
__device__ int   g_offs[NEXP];
__device__ int   g_cursor[NEXP];
__device__ float g_sumprob[NEXP];
__device__ float g_zsum;

__device__ __forceinline__ float gelu_exact(float v) {
    return 0.5f * v * (1.0f + erff(v * 0.70710678118654752f));
}

__device__ __forceinline__ uint32_t smem_u32(const void* p) {
    uint32_t a;
    asm("{ .reg .u64 t; cvta.to.shared.u64 t, %1; cvt.u32.u64 %0, t; }" : "=r"(a) : "l"(p));
    return a;
}
__device__ __forceinline__ void cp16(uint32_t dst, const void* src) {
    asm volatile("cp.async.cg.shared.global [%0], [%1], 16;" :: "r"(dst), "l"(src));
}
__device__ __forceinline__ uint32_t pack_bf16x2(float a, float b) {
    __nv_bfloat16 ha = __float2bfloat16(a);
    __nv_bfloat16 hb = __float2bfloat16(b);
    return (uint32_t)__bfloat16_as_ushort(ha) | ((uint32_t)__bfloat16_as_ushort(hb) << 16);
}

// ---------------- init / router / scan / scatter -----------------------------
__global__ void init_kernel() {
    int i = threadIdx.x;
    if (i < NEXP) { g_counts[i] = 0; g_cursor[i] = 0; g_sumprob[i] = 0.0f; }
    if (i == 0)   { g_zsum = 0.0f; }
}

__global__ void router_kernel(const float* __restrict__ x,
                              const float* __restrict__ Wr) {
    __shared__ float wr_s[DIM * NEXP];
    __shared__ float s_prob[NEXP];
    __shared__ float s_z;
    for (int i = threadIdx.x; i < DIM * NEXP; i += blockDim.x) wr_s[i] = Wr[i];
    if (threadIdx.x < NEXP) s_prob[threadIdx.x] = 0.0f;
    if (threadIdx.x == 0)   s_z = 0.0f;
    __syncthreads();
    const int warp = threadIdx.x >> 5;
    const int lane = threadIdx.x & 31;
    const int WPB  = blockDim.x >> 5;
    for (int t = blockIdx.x * WPB + warp; t < T_TOK; t += gridDim.x * WPB) {
        float acc[NEXP];
        #pragma unroll
        for (int e = 0; e < NEXP; e++) acc[e] = 0.0f;
        const float4* xr = (const float4*)(x + (size_t)t * DIM);
        #pragma unroll
        for (int i = 0; i < DIM / 128; i++) {
            float4 v = xr[i * 32 + lane];
            int d0 = i * 128 + lane * 4;
            const float* vp = &v.x;
            #pragma unroll
            for (int j = 0; j < 4; j++) {
                float xv = vp[j];
                const float* w = &wr_s[(d0 + j) * NEXP];
                #pragma unroll
                for (int e = 0; e < NEXP; e++) acc[e] += xv * w[e];
            }
        }
        #pragma unroll
        for (int e = 0; e < NEXP; e++) {
            #pragma unroll
            for (int o = 16; o > 0; o >>= 1)
                acc[e] += __shfl_xor_sync(0xffffffffu, acc[e], o);
        }
        if (lane == 0) {
            float m = acc[0];
            #pragma unroll
            for (int e = 1; e < NEXP; e++) m = fmaxf(m, acc[e]);
            float denom = 0.0f;
            float p[NEXP];
            #pragma unroll
            for (int e = 0; e < NEXP; e++) { p[e] = expf(acc[e] - m); denom += p[e]; }
            float inv = 1.0f / denom;
            #pragma unroll
            for (int e = 0; e < NEXP; e++) p[e] *= inv;
            float lse = m + logf(denom);
            atomicAdd(&s_z, lse * lse);
            #pragma unroll
            for (int e = 0; e < NEXP; e++) atomicAdd(&s_prob[e], p[e]);
            int e0 = 0;
            #pragma unroll
            for (int e = 1; e < NEXP; e++) if (p[e] > p[e0]) e0 = e;
            int e1 = (e0 == 0) ? 1 : 0;
            #pragma unroll
            for (int e = 0; e < NEXP; e++)
                if (e != e0 && p[e] > p[e1]) e1 = e;
            float s = p[e0] + p[e1] + 1e-8f;
            g_eid[2 * t]      = e0;
            g_eid[2 * t + 1]  = e1;
            g_gate[2 * t]     = p[e0] / s;
            g_gate[2 * t + 1] = p[e1] / s;
            atomicAdd(&g_counts[e0], 1);
            atomicAdd(&g_counts[e1], 1);
        }
    }
    __syncthreads();
    if (threadIdx.x < NEXP) atomicAdd(&g_sumprob[threadIdx.x], s_prob[threadIdx.x]);
    if (threadIdx.x == 0)   atomicAdd(&g_zsum, s_z);
}

__global__ void scan_kernel() {
    if (threadIdx.x == 0 && blockIdx.x == 0) {
        int o = 0;
        for (int e = 0; e < NEXP; e++) { g_offs[e] = o; g_cursor[e] = o; o += g_counts[e]; }
    }
}

__global__ void scatter_kernel() {
    int i = blockIdx.x * blockDim.x + threadIdx.x;
    if (i < NPAIR) {
        int e   = g_eid[i];
        int pos = atomicAdd(&g_cursor[e], 1);
        g_rows[pos] = i >> 1;
        g_ppos[i]   = pos;
    }
}

// ---------------- fp32 -> bf16 hi/lo split ----------------------------------
__global__ void split_kernel(const float* __restrict__ src,
                             __nv_bfloat16* __restrict__ hi,
                             __nv_bfloat16* __restrict__ lo, int n4) {
    for (int i = blockIdx.x * blockDim.x + threadIdx.x; i < n4;
         i += gridDim.x * blockDim.x) {
        float4 v = ((const float4*)src)[i];
        const float* vp = &v.x;
        uint32_t hw[2], lw[2];
        #pragma unroll
        for (int q = 0; q < 2; q++) {
            float a = vp[2 * q], b = vp[2 * q + 1];
            __nv_bfloat16 ha = __float2bfloat16(a);
            __nv_bfloat16 hb = __float2bfloat16(b);
            hw[q] = (uint32_t)__bfloat16_as_ushort(ha) | ((uint32_t)__bfloat16_as_ushort(hb) << 16);
            lw[q] = pack_bf16x2(a - __bfloat162float(ha), b - __bfloat162float(hb));
        }
        ((uint2*)hi)[i] = make_uint2(hw[0], hw[1]);
        ((uint2*)lo)[i] = make_uint2(lw[0], lw[1]);
    }
}

// ---------------- mma.sync bf16 split GEMM: 128M x 128N per CTA --------------
// D = A*W (+bias), A gathered rows, W native [K][N]. 3 passes:
//   AhiWhi + AloWhi + AhiWlo, fp32 accum.
template <int KTOT, int NTOT, bool FF1>
__global__ void __launch_bounds__(256)
moe_gemm(const __nv_bfloat16* __restrict__ Ahi, const __nv_bfloat16* __restrict__ Alo,
         const __nv_bfloat16* __restrict__ Whi, const __nv_bfloat16* __restrict__ Wlo,
         const float* __restrict__ bias) {
    const int e   = blockIdx.z;
    const int cnt = g_counts[e];
    const int m0  = blockIdx.y * 128;
    if (m0 >= cnt) return;
    const int n0  = blockIdx.x * 128;
    const int seg = g_offs[e];

    extern __shared__ char smem[];
    const uint32_t sb = smem_u32(smem);

    const int tid  = threadIdx.x;
    const int wid  = tid >> 5;
    const int lane = tid & 31;
    const int wm   = wid & 1;        // warp M (0..1) -> 64 rows
    const int wn   = wid >> 1;       // warp N (0..3) -> 32 cols

    // ---- global load slots ----
    const int ar0 = tid >> 2;        // A row (and +64)
    const int ac  = tid & 3;         // A 16B chunk (k offset ac*8)
    size_t aBase[2];
    uint32_t aDst[2];
    #pragma unroll
    for (int j = 0; j < 2; j++) {
        int r = ar0 + j * 64;
        int m = min(m0 + r, cnt - 1);
        int rowIdx = FF1 ? g_rows[seg + m] : (seg + m);
        aBase[j] = (size_t)rowIdx * KTOT + ac * 8;
        aDst[j]  = (uint32_t)((r * LDA + ac * 8) * 2);
    }
    const int br = tid >> 3;         // B k-row (0..31)
    const int bc = tid & 7;          // B chunk (and +8)
    size_t bBase[2];
    uint32_t bDst[2];
    #pragma unroll
    for (int j = 0; j < 2; j++) {
        bBase[j] = (size_t)(e * KTOT + br) * NTOT + n0 + (bc + j * 8) * 8;
        bDst[j]  = (uint32_t)(B_HI_OFF + (br * LDB + (bc + j * 8) * 8) * 2);
    }

    auto load_stage = [&](int s, int buf) {
        const uint32_t st = sb + (uint32_t)buf * STAGE_B;
        const size_t ka = (size_t)s * BK;          // element offset in K
        #pragma unroll
        for (int j = 0; j < 2; j++) {
            cp16(st + aDst[j],            Ahi + aBase[j] + ka);
            cp16(st + aDst[j] + A_LO_OFF, Alo + aBase[j] + ka);
            cp16(st + bDst[j],            Whi + bBase[j] + ka * NTOT);
            cp16(st + bDst[j] + 8704,     Wlo + bBase[j] + ka * NTOT);
        }
        asm volatile("cp.async.commit_group;" ::: "memory");
    };

    float acc[4][4][4];
    #pragma unroll
    for (int i = 0; i < 4; i++)
        #pragma unroll
        for (int j = 0; j < 4; j++)
            #pragma unroll
            for (int r = 0; r < 4; r++) acc[i][j][r] = 0.0f;

    constexpr int S = KTOT / BK;
    load_stage(0, 0);

    for (int s = 0; s < S; s++) {
        const int cur = s & 1;
        if (s + 1 < S) {
            load_stage(s + 1, cur ^ 1);
            asm volatile("cp.async.wait_group 1;" ::: "memory");
        } else {
            asm volatile("cp.async.wait_group 0;" ::: "memory");
        }
        __syncthreads();

        const uint32_t st = sb + (uint32_t)cur * STAGE_B;
        #pragma unroll
        for (int ks = 0; ks < 2; ks++) {
            uint32_t ah[4][4], al[4][4], bh[4][2], bl[4][2];
            #pragma unroll
            for (int ma = 0; ma < 4; ma++) {
                uint32_t ad = st + (uint32_t)((((wm * 64 + ma * 16 + (lane & 15)) * LDA)
                                 + ks * 16 + ((lane >> 4) * 8)) * 2);
                asm volatile("ldmatrix.sync.aligned.m8n8.x4.shared.b16 {%0,%1,%2,%3}, [%4];"
                    : "=r"(ah[ma][0]), "=r"(ah[ma][1]), "=r"(ah[ma][2]), "=r"(ah[ma][3])
                    : "r"(ad));
                asm volatile("ldmatrix.sync.aligned.m8n8.x4.shared.b16 {%0,%1,%2,%3}, [%4];"
                    : "=r"(al[ma][0]), "=r"(al[ma][1]), "=r"(al[ma][2]), "=r"(al[ma][3])
                    : "r"(ad + A_LO_OFF));
            }
            #pragma unroll
            for (int na = 0; na < 4; na++) {
                uint32_t bd = st + (uint32_t)(B_HI_OFF + (((ks * 16 + (lane & 15)) * LDB)
                                 + wn * 32 + na * 8) * 2);
                asm volatile("ldmatrix.sync.aligned.m8n8.x2.trans.shared.b16 {%0,%1}, [%2];"
                    : "=r"(bh[na][0]), "=r"(bh[na][1]) : "r"(bd));
                asm volatile("ldmatrix.sync.aligned.m8n8.x2.trans.shared.b16 {%0,%1}, [%2];"
                    : "=r"(bl[na][0]), "=r"(bl[na][1]) : "r"(bd + 8704));
            }
            #pragma unroll
            for (int p = 0; p < 3; p++) {
                #pragma unroll
                for (int ma = 0; ma < 4; ma++) {
                    #pragma unroll
                    for (int na = 0; na < 4; na++) {
                        const uint32_t* A = (p == 1) ? al[ma] : ah[ma];
                        const uint32_t* B = (p == 2) ? bl[na] : bh[na];
                        float* C = acc[ma][na];
                        asm volatile(
                            "mma.sync.aligned.m16n8k16.row.col.f32.bf16.bf16.f32 "
                            "{%0,%1,%2,%3}, {%4,%5,%6,%7}, {%8,%9}, {%0,%1,%2,%3};"
                            : "+f"(C[0]), "+f"(C[1]), "+f"(C[2]), "+f"(C[3])
                            : "r"(A[0]), "r"(A[1]), "r"(A[2]), "r"(A[3]),
                              "r"(B[0]), "r"(B[1]));
                    }
                }
            }
        }
        __syncthreads();
    }

    // ---- epilogue ----
    const int r0l = lane >> 2;
    const int c0l = (lane & 3) * 2;
    #pragma unroll
    for (int ma = 0; ma < 4; ma++) {
        #pragma unroll
        for (int rr = 0; rr < 2; rr++) {
            int lm = wm * 64 + ma * 16 + r0l + rr * 8;
            int m = m0 + lm;
            if (m >= cnt) continue;
            #pragma unroll
            for (int na = 0; na < 4; na++) {
                int col = n0 + wn * 32 + na * 8 + c0l;
                float b0 = bias[(size_t)e * NTOT + col];
                float b1 = bias[(size_t)e * NTOT + col + 1];
                float v0 = acc[ma][na][rr * 2 + 0] + b0;
                float v1 = acc[ma][na][rr * 2 + 1] + b1;
                if (FF1) {
                    v0 = gelu_exact(v0);
                    v1 = gelu_exact(v1);
                    __nv_bfloat16 h0 = __float2bfloat16(v0);
                    __nv_bfloat16 h1 = __float2bfloat16(v1);
                    uint32_t hw = (uint32_t)__bfloat16_as_ushort(h0) |
                                  ((uint32_t)__bfloat16_as_ushort(h1) << 16);
                    uint32_t lw = pack_bf16x2(v0 - __bfloat162float(h0),
                                              v1 - __bfloat162float(h1));
                    size_t off = (size_t)(seg + m) * NTOT + col;
                    *(uint32_t*)(g_Hhi + off) = hw;
                    *(uint32_t*)(g_Hlo + off) = lw;
                } else {
                    float2 o; o.x = v0; o.y = v1;
                    *(float2*)(g_Y + (size_t)(seg + m) * NTOT + col) = o;
                }
            }
        }
    }
}

// ---------------- combine + finalize ----------------------------------------
__global__ void combine_kernel(float* __restrict__ out) {
    const int NV = NOUT / 4;
    int idx = blockIdx.x * blockDim.x + threadIdx.x;
    if (idx >= NV) return;
    int t = idx / (DIM / 4);
    int q = idx % (DIM / 4);
    int p0 = g_ppos[2 * t], p1 = g_ppos[2 * t + 1];
    float g0 = g_gate[2 * t], g1 = g_gate[2 * t + 1];
    float4 y0 = ((const float4*)(g_Y + (size_t)p0 * DIM))[q];
    float4 y1 = ((const float4*)(g_Y + (size_t)p1 * DIM))[q];
    float4 o;
    o.x = g0 * y0.x + g1 * y1.x;
    o.y = g0 * y0.y + g1 * y1.y;
    o.z = g0 * y0.z + g1 * y1.z;
    o.w = g0 * y0.w + g1 * y1.w;
    ((float4*)out)[idx] = o;
}

__global__ void finalize_kernel(float* __restrict__ out, int out_size) {
    if (threadIdx.x != 0 || blockIdx.x != 0) return;
    float u[NEXP];
    float mean = 0.0f;
    #pragma unroll
    for (int e = 0; e < NEXP; e++) { u[e] = g_sumprob[e] / (float)T_TOK; mean += u[e]; }
    mean /= (float)NEXP;
    float var = 0.0f;
    #pragma unroll
    for (int e = 0; e < NEXP; e++) { float dd = u[e] - mean; var += dd * dd; }
    var /= (float)NEXP;
    float lb = var / (mean * mean + 1e-8f) * (float)NEXP * 0.01f;
    float z  = (g_zsum / (float)T_TOK) * 0.001f;
    if (out_size >= NOUT + 1) out[NOUT] = lb;
    if (out_size >= NOUT + 2) out[NOUT + 1] = z;
}

// ---------------- launch ------------------------------------------------------
extern "C" void kernel_launch(void* const* d_in, const int* in_sizes, int n_in,
                              void* d_out, int out_size) {
    const float* x  = (const float*)d_in[0];
    const float* Wr = (const float*)d_in[1];
    const float* W1 = (const float*)d_in[2];
    const float* b1 = (const float*)d_in[3];
    const float* W2 = (const float*)d_in[4];
    const float* b2 = (const float*)d_in[5];
    float* out = (float*)d_out;
    (void)in_sizes; (void)n_in;

    cudaFuncSetAttribute(moe_gemm<DIM, FDIM, true>,
                         cudaFuncAttributeMaxDynamicSharedMemorySize, SMEM_BYTES);
    cudaFuncSetAttribute(moe_gemm<FDIM, DIM, false>,
                         cudaFuncAttributeMaxDynamicSharedMemorySize, SMEM_BYTES);

    init_kernel<<<1, 32>>>();
    router_kernel<<<128, 256>>>(x, Wr);
    scan_kernel<<<1, 32>>>();
    scatter_kernel<<<(NPAIR + 255) / 256, 256>>>();

    __nv_bfloat16 *xhi, *xlo, *w1hi, *w1lo, *w2hi, *w2lo, *hhi, *hlo;
    cudaGetSymbolAddress((void**)&xhi,  g_Xhi);
    cudaGetSymbolAddress((void**)&xlo,  g_Xlo);
    cudaGetSymbolAddress((void**)&w1hi, g_W1hi);
    cudaGetSymbolAddress((void**)&w1lo, g_W1lo);
    cudaGetSymbolAddress((void**)&w2hi, g_W2hi);
    cudaGetSymbolAddress((void**)&w2lo, g_W2lo);
    cudaGetSymbolAddress((void**)&hhi,  g_Hhi);
    cudaGetSymbolAddress((void**)&hlo,  g_Hlo);

    split_kernel<<<1184, 256>>>(x,  xhi,  xlo,  T_TOK * DIM / 4);
    split_kernel<<<1184, 256>>>(W1, w1hi, w1lo, NEXP * DIM * FDIM / 4);
    split_kernel<<<1184, 256>>>(W2, w2hi, w2lo, NEXP * FDIM * DIM / 4);

    dim3 g1(FDIM / 128, NPAIR / 128, NEXP);   // (24, 128, 8)
    moe_gemm<DIM, FDIM, true><<<g1, 256, SMEM_BYTES>>>(xhi, xlo, w1hi, w1lo, b1);
    dim3 g2(DIM / 128, NPAIR / 128, NEXP);    // (6, 128, 8)
    moe_gemm<FDIM, DIM, false><<<g2, 256, SMEM_BYTES>>>(hhi, hlo, w2hi, w2lo, b2);

    combine_kernel<<<(NOUT / 4 + 255) / 256, 256>>>(out);
    finalize_kernel<<<1, 32>>>(out, out_size);
}